// round 8
// baseline (speedup 1.0000x reference)
#include <cuda_runtime.h>
#include <cfloat>

#define B   32
#define C   512
#define H   56
#define W   56
#define HW  (H * W)          // 3136
#define HW4 (HW / 4)         // 784
#define KD  768
#define NTOT ((size_t)B * C * HW)

// pooling block geometry: 16 hw4-columns x 16 channel-chunks (R6-proven)
#define PTX 16
#define PTY 16
#define PCC (C / PTY)        // 32 channels per thread
#define PBLK_PER_B (HW4 / PTX)   // 49

// conv tail tile: zero-padded [2][62][64]
#define TTH 62
#define TTW 64

// Scratch (alloc-free rule: __device__ globals; zero-initialized at load)
__device__ float g_pooled[B * 2 * HW];
__device__ float g_scale[B * HW];
__device__ int   g_done[B];              // self-resetting per launch

// ---------------------------------------------------------------------------
// Kernel 1: fused channel max+mean pooling + ATOMIC-TAIL conv.
// Pool phase: R6-proven (256 thr, 32-ch columns, smem tree reduce).
// Tail phase: last-finishing block per batch computes the 7x7 conv + keyword
// bias + sigmoid for the whole batch from an smem copy of the pooled map.
// ---------------------------------------------------------------------------
__global__ void __launch_bounds__(PTX * PTY)
pool_conv_kernel(const float4* __restrict__ x4,
                 const float* __restrict__ conv_w,
                 const float* __restrict__ conv_b,
                 const float* __restrict__ keyword,
                 const float* __restrict__ proj_w,
                 const float* __restrict__ proj_b) {
    // union: pool-reduce buffers (8 KB) alias the conv tile (31 KB)
    __shared__ char  ubuf[2 * TTH * TTW * 4];
    __shared__ float wts[98];
    __shared__ float wsum[8];
    __shared__ float sbias;
    __shared__ int   s_tail;

    float4 (*smax)[PTX] = reinterpret_cast<float4(*)[PTX]>(ubuf);
    float4 (*ssum)[PTX] = reinterpret_cast<float4(*)[PTX]>(ubuf + sizeof(float4) * PTY * PTX);
    float  (*tile)[TTH][TTW] = reinterpret_cast<float(*)[TTH][TTW]>(ubuf);

    int tid = threadIdx.x;
    int tx  = tid & (PTX - 1);
    int ty  = tid >> 4;
    int b   = blockIdx.y;
    int hw4 = blockIdx.x * PTX + tx;

    // ---- pool phase ----
    const float4* p = x4 + (size_t)b * C * HW4 + (size_t)ty * PCC * HW4 + hw4;
    float4 v0 = __ldg(p);
    float4 mx = v0;
    float4 sm = v0;
#pragma unroll
    for (int c = 1; c < PCC; ++c) {
        float4 v = __ldg(p + (size_t)c * HW4);
        mx.x = fmaxf(mx.x, v.x); mx.y = fmaxf(mx.y, v.y);
        mx.z = fmaxf(mx.z, v.z); mx.w = fmaxf(mx.w, v.w);
        sm.x += v.x; sm.y += v.y; sm.z += v.z; sm.w += v.w;
    }

    smax[ty][tx] = mx;
    ssum[ty][tx] = sm;
    __syncthreads();

#pragma unroll
    for (int s = PTY / 2; s > 0; s >>= 1) {
        if (ty < s) {
            float4 m = smax[ty + s][tx];
            float4 q = ssum[ty + s][tx];
            mx.x = fmaxf(mx.x, m.x); mx.y = fmaxf(mx.y, m.y);
            mx.z = fmaxf(mx.z, m.z); mx.w = fmaxf(mx.w, m.w);
            sm.x += q.x; sm.y += q.y; sm.z += q.z; sm.w += q.w;
            smax[ty][tx] = mx;
            ssum[ty][tx] = sm;
        }
        __syncthreads();
    }

    if (ty == 0) {
        const float inv = 1.0f / C;
        sm.x *= inv; sm.y *= inv; sm.z *= inv; sm.w *= inv;
        float4* pool4 = reinterpret_cast<float4*>(g_pooled);
        pool4[(b * 2 * HW) / 4 + hw4]      = mx;
        pool4[(b * 2 * HW + HW) / 4 + hw4] = sm;
    }
    __syncthreads();   // all pooled stores issued before the fence below

    // ---- elect tail block for this batch ----
    if (tid == 0) {
        __threadfence();                      // publish pooled writes
        int old = atomicAdd(&g_done[b], 1);
        int tail = (old == PBLK_PER_B - 1);
        if (tail) g_done[b] = 0;              // reset for next graph replay
        s_tail = tail;
    }
    __syncthreads();
    if (!s_tail) return;
    __threadfence();                          // acquire other blocks' writes

    // ---- conv tail phase (one block per batch) ----
    if (tid < 98) wts[tid] = conv_w[tid];

    // keyword bias dot
    {
        float s = 0.0f;
        const float* kb = keyword + b * KD;
        for (int k = tid; k < KD; k += PTX * PTY)
            s += __ldcg(kb + k) * __ldcg(proj_w + k);
#pragma unroll
        for (int off = 16; off > 0; off >>= 1)
            s += __shfl_down_sync(0xFFFFFFFFu, s, off);
        if ((tid & 31) == 0) wsum[tid >> 5] = s;
    }

    // load zero-padded pooled tile [2][62][64] (bypass L1: other SMs wrote it)
    const float* pb = g_pooled + b * 2 * HW;
    for (int i = tid; i < 2 * TTH * TTW; i += PTX * PTY) {
        int ci = i / (TTH * TTW);
        int rr = (i / TTW) % TTH;
        int cc = i % TTW;
        int hh = rr - 3;
        int ww = cc - 3;
        float v = 0.0f;
        if ((unsigned)hh < (unsigned)H && (unsigned)ww < (unsigned)W)
            v = __ldcg(pb + ci * HW + hh * W + ww);
        tile[ci][rr][cc] = v;
    }
    __syncthreads();

    if (tid == 0) {
        float t = 0.0f;
#pragma unroll
        for (int i = 0; i < 8; ++i) t += wsum[i];
        sbias = t + __ldcg(proj_b) + __ldcg(conv_b);
    }
    __syncthreads();

    // 3136 outputs over 256 threads
    for (int o = tid; o < HW; o += PTX * PTY) {
        int h = o / W;
        int w = o - h * W;
        float acc = sbias;
#pragma unroll
        for (int ci = 0; ci < 2; ++ci) {
#pragma unroll
            for (int kh = 0; kh < 7; ++kh) {
#pragma unroll
                for (int kw = 0; kw < 7; ++kw) {
                    acc += tile[ci][h + kh][w + kw] * wts[ci * 49 + kh * 7 + kw];
                }
            }
        }
        g_scale[b * HW + o] = 1.0f / (1.0f + __expf(-acc));
    }
}

// ---------------------------------------------------------------------------
// Kernel 2: out = x * scale (broadcast over C). float4 streaming (proven).
// ---------------------------------------------------------------------------
__global__ void mul_kernel(const float4* __restrict__ x4,
                           float4* __restrict__ out4) {
    const int CHW4 = C * HW4;
    int i = blockIdx.x * blockDim.x + threadIdx.x;
    if (i >= (int)(NTOT / 4)) return;
    int b   = i / CHW4;
    int rem = i - b * CHW4;
    int hw4 = rem % HW4;

    float4 s = reinterpret_cast<const float4*>(g_scale)[b * HW4 + hw4];
    float4 v = __ldcs(x4 + i);
    v.x *= s.x; v.y *= s.y; v.z *= s.z; v.w *= s.w;
    __stcs(out4 + i, v);
}

// ---------------------------------------------------------------------------
extern "C" void kernel_launch(void* const* d_in, const int* in_sizes, int n_in,
                              void* d_out, int out_size) {
    const float* x       = (const float*)d_in[0];
    const float* keyword = (const float*)d_in[1];
    const float* conv_w  = (const float*)d_in[2];
    const float* conv_b  = (const float*)d_in[3];
    const float* proj_w  = (const float*)d_in[4];
    const float* proj_b  = (const float*)d_in[5];
    float* out = (float*)d_out;

    {
        dim3 grid(PBLK_PER_B, B);        // 49 x 32
        pool_conv_kernel<<<grid, PTX * PTY>>>((const float4*)x, conv_w, conv_b,
                                              keyword, proj_w, proj_b);
    }
    {
        int n4 = (int)(NTOT / 4);
        mul_kernel<<<(n4 + 255) / 256, 256>>>((const float4*)x, (float4*)out);
    }
}

// round 9
// speedup vs baseline: 1.0921x; 1.0921x over previous
#include <cuda_runtime.h>
#include <cfloat>

#define B   32
#define C   512
#define H   56
#define W   56
#define HW  (H * W)          // 3136
#define HW4 (HW / 4)         // 784
#define KD  768
#define NTOT ((size_t)B * C * HW)

// pooling block geometry: 16 hw4-columns x 16 channel-chunks (R6-proven)
#define PTX 16
#define PTY 16
#define PCC (C / PTY)        // 32 channels per thread
#define PBLK_PER_B (HW4 / PTX)   // 49

// conv tiling
#define CROWS 4
#define CTH   (CROWS + 6)
#define CTW   64

// Scratch (alloc-free rule: __device__ globals)
__device__ float g_pooled[B * 2 * HW];
__device__ float g_scale[B * HW];

// ---------------------------------------------------------------------------
// Kernel 1: fused channel max+mean pooling (R6-proven geometry).
// ---------------------------------------------------------------------------
__global__ void __launch_bounds__(PTX * PTY)
pool_kernel(const float4* __restrict__ x4) {
    int tx = threadIdx.x & (PTX - 1);
    int ty = threadIdx.x >> 4;
    int b   = blockIdx.y;
    int hw4 = blockIdx.x * PTX + tx;

    const float4* p = x4 + (size_t)b * C * HW4
                         + (size_t)ty * PCC * HW4 + hw4;
    float4 v0 = __ldg(p);
    float4 mx = v0;
    float4 sm = v0;
#pragma unroll
    for (int c = 1; c < PCC; ++c) {
        float4 v = __ldg(p + (size_t)c * HW4);
        mx.x = fmaxf(mx.x, v.x); mx.y = fmaxf(mx.y, v.y);
        mx.z = fmaxf(mx.z, v.z); mx.w = fmaxf(mx.w, v.w);
        sm.x += v.x; sm.y += v.y; sm.z += v.z; sm.w += v.w;
    }

    __shared__ float4 smax[PTY][PTX];
    __shared__ float4 ssum[PTY][PTX];
    smax[ty][tx] = mx;
    ssum[ty][tx] = sm;
    __syncthreads();

#pragma unroll
    for (int s = PTY / 2; s > 0; s >>= 1) {
        if (ty < s) {
            float4 m = smax[ty + s][tx];
            float4 q = ssum[ty + s][tx];
            mx.x = fmaxf(mx.x, m.x); mx.y = fmaxf(mx.y, m.y);
            mx.z = fmaxf(mx.z, m.z); mx.w = fmaxf(mx.w, m.w);
            sm.x += q.x; sm.y += q.y; sm.z += q.z; sm.w += q.w;
            smax[ty][tx] = mx;
            ssum[ty][tx] = sm;
        }
        __syncthreads();
    }

    if (ty == 0) {
        const float inv = 1.0f / C;
        sm.x *= inv; sm.y *= inv; sm.z *= inv; sm.w *= inv;
        float4* pool4 = reinterpret_cast<float4*>(g_pooled);
        pool4[(b * 2 * HW) / 4 + hw4]      = mx;
        pool4[(b * 2 * HW + HW) / 4 + hw4] = sm;
    }
#if __CUDA_ARCH__ >= 900
    cudaTriggerProgrammaticLaunchCompletion();
#endif
}

// ---------------------------------------------------------------------------
// Kernel 2: smem-tiled 7x7 conv + sigmoid + keyword bias (R6-proven), with
// PDL: prologue (keyword dot, weight load) overlaps pool; grid-dep-sync
// before reading g_pooled.
// ---------------------------------------------------------------------------
__global__ void conv_kernel(const float* __restrict__ conv_w,
                            const float* __restrict__ conv_b,
                            const float* __restrict__ keyword,
                            const float* __restrict__ proj_w,
                            const float* __restrict__ proj_b) {
    __shared__ float tile[2][CTH][CTW];   // 5 KB
    __shared__ float wts[98];
    __shared__ float wsum[8];
    __shared__ float sbias;

    int b  = blockIdx.y;
    int r0 = blockIdx.x * CROWS;
    int tid = threadIdx.x;

    // -------- pre-sync region: independent of pool --------
    if (tid < 98) wts[tid] = conv_w[tid];
    {
        float s = 0.0f;
        const float* kb = keyword + b * KD;
#pragma unroll
        for (int k = tid; k < KD; k += 256)
            s += kb[k] * proj_w[k];
#pragma unroll
        for (int off = 16; off > 0; off >>= 1)
            s += __shfl_down_sync(0xFFFFFFFFu, s, off);
        if ((tid & 31) == 0) wsum[tid >> 5] = s;
    }
    if (tid == 0) sbias = proj_b[0] + conv_b[0];

#if __CUDA_ARCH__ >= 900
    cudaGridDependencySynchronize();      // wait for pool's g_pooled
#endif

    // -------- post-sync: pooled tile load + conv --------
    const float* pb = g_pooled + b * 2 * HW;
    for (int i = tid; i < 2 * CTH * CTW; i += 256) {
        int ci = i / (CTH * CTW);
        int rr = (i / CTW) % CTH;
        int cc = i % CTW;
        int hh = r0 + rr - 3;
        int ww = cc - 3;
        float v = 0.0f;
        if ((unsigned)hh < (unsigned)H && (unsigned)ww < (unsigned)W)
            v = pb[ci * HW + hh * W + ww];
        tile[ci][rr][cc] = v;
    }
    __syncthreads();

    if (tid == 0) {
        float t = sbias;
#pragma unroll
        for (int i = 0; i < 8; ++i) t += wsum[i];
        sbias = t;
    }
    __syncthreads();

    if (tid < CROWS * W) {
        int r = tid / W;
        int w = tid - r * W;
        float acc = sbias;
#pragma unroll
        for (int ci = 0; ci < 2; ++ci) {
#pragma unroll
            for (int kh = 0; kh < 7; ++kh) {
#pragma unroll
                for (int kw = 0; kw < 7; ++kw) {
                    acc += tile[ci][r + kh][w + kw] * wts[ci * 49 + kh * 7 + kw];
                }
            }
        }
        g_scale[b * HW + (r0 + r) * W + w] = 1.0f / (1.0f + __expf(-acc));
    }
#if __CUDA_ARCH__ >= 900
    cudaTriggerProgrammaticLaunchCompletion();
#endif
}

// ---------------------------------------------------------------------------
// Kernel 3: out = x * scale. PDL: x load (pool/conv-independent) issues
// before grid-dep-sync; scale read + store after.
// ---------------------------------------------------------------------------
__global__ void mul_kernel(const float4* __restrict__ x4,
                           float4* __restrict__ out4) {
    const int CHW4 = C * HW4;
    int i = blockIdx.x * blockDim.x + threadIdx.x;
    bool active = (i < (int)(NTOT / 4));

    float4 v = make_float4(0.f, 0.f, 0.f, 0.f);
    int b = 0, hw4 = 0;
    if (active) {
        b       = i / CHW4;
        int rem = i - b * CHW4;
        hw4     = rem % HW4;
        v = __ldcs(x4 + i);               // overlaps conv execution
    }

#if __CUDA_ARCH__ >= 900
    cudaGridDependencySynchronize();      // wait for conv's g_scale
#endif

    if (active) {
        float4 s = reinterpret_cast<const float4*>(g_scale)[b * HW4 + hw4];
        v.x *= s.x; v.y *= s.y; v.z *= s.z; v.w *= s.w;
        __stcs(out4 + i, v);
    }
}

// ---------------------------------------------------------------------------
static void launch_pdl(void* fn, dim3 grid, dim3 block, void** args) {
    cudaLaunchAttribute attr[1];
    attr[0].id = cudaLaunchAttributeProgrammaticStreamSerialization;
    attr[0].val.programmaticStreamSerializationAllowed = 1;
    cudaLaunchConfig_t cfg{};
    cfg.gridDim  = grid;
    cfg.blockDim = block;
    cfg.dynamicSmemBytes = 0;
    cfg.stream   = 0;                     // legacy default stream (captured)
    cfg.attrs    = attr;
    cfg.numAttrs = 1;
    cudaLaunchKernelExC(&cfg, fn, args);
}

extern "C" void kernel_launch(void* const* d_in, const int* in_sizes, int n_in,
                              void* d_out, int out_size) {
    const float* x       = (const float*)d_in[0];
    const float* keyword = (const float*)d_in[1];
    const float* conv_w  = (const float*)d_in[2];
    const float* conv_b  = (const float*)d_in[3];
    const float* proj_w  = (const float*)d_in[4];
    const float* proj_b  = (const float*)d_in[5];
    float* out = (float*)d_out;

    // 1) pool (plain launch)
    {
        dim3 grid(PBLK_PER_B, B);
        const float4* xa = (const float4*)x;
        void* args[] = { (void*)&xa };
        cudaLaunchConfig_t cfg{};
        cfg.gridDim = grid; cfg.blockDim = dim3(PTX * PTY);
        cfg.stream = 0; cfg.attrs = nullptr; cfg.numAttrs = 0;
        cudaLaunchKernelExC(&cfg, (void*)pool_kernel, args);
    }
    // 2) conv (PDL after pool)
    {
        dim3 grid(H / CROWS, B);
        void* args[] = { (void*)&conv_w, (void*)&conv_b, (void*)&keyword,
                         (void*)&proj_w, (void*)&proj_b };
        launch_pdl((void*)conv_kernel, grid, dim3(256), args);
    }
    // 3) mul (PDL after conv)
    {
        int n4 = (int)(NTOT / 4);
        dim3 grid((n4 + 255) / 256);
        const float4* xa = (const float4*)x;
        float4* oa = (float4*)out;
        void* args[] = { (void*)&xa, (void*)&oa };
        launch_pdl((void*)mul_kernel, grid, dim3(256), args);
    }
}

// round 10
// speedup vs baseline: 1.0925x; 1.0003x over previous
#include <cuda_runtime.h>
#include <cfloat>

#define B   32
#define C   512
#define H   56
#define W   56
#define HW  (H * W)          // 3136
#define HW4 (HW / 4)         // 784
#define KD  768
#define NTOT ((size_t)B * C * HW)
#define NCOL (B * HW4)       // 25088 flattened float4 columns

// pooling block geometry: 32 flattened columns x 8 channel-chunks, 256 thr
#define PTX 32
#define PTY 8
#define PCC (C / PTY)        // 64 channels per thread
#define PGRID (NCOL / PTX)   // 784 blocks

// conv tiling
#define CROWS 4
#define CTH   (CROWS + 6)
#define CTW   64

// Scratch (alloc-free rule: __device__ globals)
__device__ float g_pooled[B * 2 * HW];
__device__ float g_scale[B * HW];

// ---------------------------------------------------------------------------
// Kernel 1: fused channel max+mean pooling, warp-contiguous loads.
// Lane l of each warp covers flattened column f = blk*32 + l, so every warp
// LDG.128 is one contiguous 512B segment. Per-lane batch decode handles the
// rare blocks that straddle a batch boundary.
// ---------------------------------------------------------------------------
__global__ void __launch_bounds__(PTX * PTY)
pool_kernel(const float4* __restrict__ x4) {
    int tx = threadIdx.x & (PTX - 1);     // lane = column within block
    int ty = threadIdx.x >> 5;            // 0..7 channel chunk
    int f  = blockIdx.x * PTX + tx;       // flattened (b, hw4)
    int b   = f / HW4;
    int hw4 = f - b * HW4;

    const float4* p = x4 + (size_t)b * C * HW4
                         + (size_t)ty * PCC * HW4 + hw4;
    float4 v0 = __ldg(p);
    float4 mx = v0;
    float4 sm = v0;
#pragma unroll 16
    for (int c = 1; c < PCC; ++c) {
        float4 v = __ldg(p + (size_t)c * HW4);
        mx.x = fmaxf(mx.x, v.x); mx.y = fmaxf(mx.y, v.y);
        mx.z = fmaxf(mx.z, v.z); mx.w = fmaxf(mx.w, v.w);
        sm.x += v.x; sm.y += v.y; sm.z += v.z; sm.w += v.w;
    }

    __shared__ float4 smax[PTY][PTX];
    __shared__ float4 ssum[PTY][PTX];
    smax[ty][tx] = mx;
    ssum[ty][tx] = sm;
    __syncthreads();

#pragma unroll
    for (int s = PTY / 2; s > 0; s >>= 1) {
        if (ty < s) {
            float4 m = smax[ty + s][tx];
            float4 q = ssum[ty + s][tx];
            mx.x = fmaxf(mx.x, m.x); mx.y = fmaxf(mx.y, m.y);
            mx.z = fmaxf(mx.z, m.z); mx.w = fmaxf(mx.w, m.w);
            sm.x += q.x; sm.y += q.y; sm.z += q.z; sm.w += q.w;
            smax[ty][tx] = mx;
            ssum[ty][tx] = sm;
        }
        __syncthreads();
    }

    if (ty == 0) {
        const float inv = 1.0f / C;
        sm.x *= inv; sm.y *= inv; sm.z *= inv; sm.w *= inv;
        float4* pool4 = reinterpret_cast<float4*>(g_pooled);
        pool4[(b * 2 * HW) / 4 + hw4]      = mx;
        pool4[(b * 2 * HW + HW) / 4 + hw4] = sm;
    }
}

// ---------------------------------------------------------------------------
// Kernel 2: smem-tiled 7x7 conv + sigmoid + keyword bias (R6-proven).
// grid = (14, 32), 256 threads.
// ---------------------------------------------------------------------------
__global__ void conv_kernel(const float* __restrict__ conv_w,
                            const float* __restrict__ conv_b,
                            const float* __restrict__ keyword,
                            const float* __restrict__ proj_w,
                            const float* __restrict__ proj_b) {
    __shared__ float tile[2][CTH][CTW];   // 5 KB
    __shared__ float wts[98];
    __shared__ float wsum[8];
    __shared__ float sbias;

    int b  = blockIdx.y;
    int r0 = blockIdx.x * CROWS;
    int tid = threadIdx.x;

    if (tid < 98) wts[tid] = conv_w[tid];

    {
        float s = 0.0f;
        const float* kb = keyword + b * KD;
#pragma unroll
        for (int k = tid; k < KD; k += 256)
            s += kb[k] * proj_w[k];
#pragma unroll
        for (int off = 16; off > 0; off >>= 1)
            s += __shfl_down_sync(0xFFFFFFFFu, s, off);
        if ((tid & 31) == 0) wsum[tid >> 5] = s;
    }

    const float* pb = g_pooled + b * 2 * HW;
    for (int i = tid; i < 2 * CTH * CTW; i += 256) {
        int ci = i / (CTH * CTW);
        int rr = (i / CTW) % CTH;
        int cc = i % CTW;
        int hh = r0 + rr - 3;
        int ww = cc - 3;
        float v = 0.0f;
        if ((unsigned)hh < (unsigned)H && (unsigned)ww < (unsigned)W)
            v = pb[ci * HW + hh * W + ww];
        tile[ci][rr][cc] = v;
    }
    __syncthreads();

    if (tid == 0) {
        float t = 0.0f;
#pragma unroll
        for (int i = 0; i < 8; ++i) t += wsum[i];
        sbias = t + proj_b[0] + conv_b[0];
    }
    __syncthreads();

    if (tid < CROWS * W) {
        int r = tid / W;
        int w = tid - r * W;
        float acc = sbias;
#pragma unroll
        for (int ci = 0; ci < 2; ++ci) {
#pragma unroll
            for (int kh = 0; kh < 7; ++kh) {
#pragma unroll
                for (int kw = 0; kw < 7; ++kw) {
                    acc += tile[ci][r + kh][w + kw] * wts[ci * 49 + kh * 7 + kw];
                }
            }
        }
        g_scale[b * HW + (r0 + r) * W + w] = 1.0f / (1.0f + __expf(-acc));
    }
}

// ---------------------------------------------------------------------------
// Kernel 3: out = x * scale (broadcast over C). float4 streaming (proven).
// ---------------------------------------------------------------------------
__global__ void mul_kernel(const float4* __restrict__ x4,
                           float4* __restrict__ out4) {
    const int CHW4 = C * HW4;
    int i = blockIdx.x * blockDim.x + threadIdx.x;
    if (i >= (int)(NTOT / 4)) return;
    int b   = i / CHW4;
    int rem = i - b * CHW4;
    int hw4 = rem % HW4;

    float4 s = reinterpret_cast<const float4*>(g_scale)[b * HW4 + hw4];
    float4 v = __ldcs(x4 + i);
    v.x *= s.x; v.y *= s.y; v.z *= s.z; v.w *= s.w;
    __stcs(out4 + i, v);
}

// ---------------------------------------------------------------------------
extern "C" void kernel_launch(void* const* d_in, const int* in_sizes, int n_in,
                              void* d_out, int out_size) {
    const float* x       = (const float*)d_in[0];
    const float* keyword = (const float*)d_in[1];
    const float* conv_w  = (const float*)d_in[2];
    const float* conv_b  = (const float*)d_in[3];
    const float* proj_w  = (const float*)d_in[4];
    const float* proj_b  = (const float*)d_in[5];
    float* out = (float*)d_out;

    pool_kernel<<<PGRID, PTX * PTY>>>((const float4*)x);
    {
        dim3 grid(H / CROWS, B);         // 14 x 32
        conv_kernel<<<grid, 256>>>(conv_w, conv_b, keyword, proj_w, proj_b);
    }
    {
        int n4 = (int)(NTOT / 4);
        mul_kernel<<<(n4 + 255) / 256, 256>>>((const float4*)x, (float4*)out);
    }
}